// round 1
// baseline (speedup 1.0000x reference)
#include <cuda_runtime.h>

// ST-GCN layer, restructured:
//   xwin = 9-tap causal window sum of x (commutes with all channel/joint contractions)
//   y[k=co*3+p, v] = sum_c xwin[c,v] * W[c,k]
//   t[co,w]        = sum_{p,v} y[co*3+p, v] * A[p,v,w]
//   out = relu(relu(BN(t)) + x)
// All fp32, packed f32x2 FMA (V=25 padded to 26).

#define VP 26                 // padded joint dim (pair-friendly)
#define NB 32
#define CI 64
#define LT 300
#define V  25
#define KD 192                // CO*P
#define MT 4                  // time steps per block in main kernel

// scratch: xwin[n][m][c][26]; column 25 is never written -> stays 0 (zero-init global)
__device__ float g_xwin[(size_t)NB * LT * CI * VP];

// ---------- packed f32x2 helpers ----------
__device__ __forceinline__ unsigned long long pack2(float lo, float hi) {
    unsigned long long r;
    asm("mov.b64 %0, {%1,%2};" : "=l"(r) : "f"(lo), "f"(hi));
    return r;
}
__device__ __forceinline__ void unpack2(unsigned long long v, float& lo, float& hi) {
    asm("mov.b64 {%0,%1}, %2;" : "=f"(lo), "=f"(hi) : "l"(v));
}
__device__ __forceinline__ unsigned long long ffma2(unsigned long long a,
                                                    unsigned long long b,
                                                    unsigned long long c) {
    unsigned long long d;
    asm("fma.rn.f32x2 %0, %1, %2, %3;" : "=l"(d) : "l"(a), "l"(b), "l"(c));
    return d;
}

// ---------- kernel 1: sliding window sum ----------
// one block per (n, c); stage the full (L, V) row in smem, 9-tap sum, write padded layout
__global__ __launch_bounds__(256) void win_kernel(const float* __restrict__ x) {
    int n = blockIdx.x >> 6;
    int c = blockIdx.x & 63;
    __shared__ float sx[LT * V];   // 30000 B
    const float* xp = x + ((size_t)(n * CI + c)) * LT * V;
    for (int i = threadIdx.x; i < LT * V; i += 256) sx[i] = xp[i];
    __syncthreads();
    float* ob = g_xwin + ((size_t)n * LT) * CI * VP + (size_t)c * VP;
    for (int i = threadIdx.x; i < LT * V; i += 256) {
        int m = i / V;
        int v = i - m * V;
        float s = 0.f;
        #pragma unroll
        for (int j = 0; j < 9; j++) {
            int l = m - j;
            if (l >= 0) s += sx[l * V + v];
        }
        ob[(size_t)m * CI * VP + v] = s;
    }
}

// ---------- kernel 2: fused contraction + BN + ReLU + residual ----------
// grid = NB * (LT/MT) blocks, 256 threads
// dyn smem: As (3*25*13 ull) | Wsm (64*192) | xw (64*26) | ysm (192*26) | bnA(64) | bnB(64)
#define AS_ULL   (3 * V * 13)
#define SM_FLOAT_BASE (AS_ULL * 2 + 2)          // float index of Wsm, 8B aligned, even
#define SMEM_FLOATS (SM_FLOAT_BASE + CI * KD + CI * VP + KD * VP + 128)
#define SMEM_BYTES  (SMEM_FLOATS * 4)

__global__ __launch_bounds__(256, 2) void main_kernel(
    const float* __restrict__ x,
    const float* __restrict__ A,
    const float* __restrict__ W,
    const float* __restrict__ gamma,
    const float* __restrict__ beta,
    const float* __restrict__ mean,
    const float* __restrict__ var,
    float* __restrict__ out)
{
    extern __shared__ unsigned long long smem_raw[];
    unsigned long long* As = smem_raw;                       // [3][25][13] packed w-pairs
    float* fbase = (float*)smem_raw;
    float* Wsm = fbase + SM_FLOAT_BASE;                      // [64][192]
    float* xw  = Wsm + CI * KD;                              // [64][26]
    float* ysm = xw + CI * VP;                               // [192][26]
    float* bnA = ysm + KD * VP;                              // [64]
    float* bnB = bnA + CI;                                   // [64]

    const int tid = threadIdx.x;
    const int n  = blockIdx.x / (LT / MT);
    const int m0 = (blockIdx.x % (LT / MT)) * MT;

    // block-wide init: BN constants, packed A (w padded), W staged to smem
    for (int i = tid; i < CI; i += 256) {
        float inv = gamma[i] * rsqrtf(var[i] + 1e-3f);
        bnA[i] = inv;
        bnB[i] = beta[i] - mean[i] * inv;
    }
    for (int i = tid; i < AS_ULL; i += 256) {
        int wp = i % 13, pv = i / 13;
        float a0 = A[pv * V + 2 * wp];
        float a1 = (2 * wp + 1 < V) ? A[pv * V + 2 * wp + 1] : 0.f;
        As[i] = pack2(a0, a1);
    }
    for (int i = tid; i < CI * KD; i += 256) Wsm[i] = W[i];

    const int k   = tid;          // phase-1 owner of output row k (<192 active)
    const int wp  = tid & 15;     // phase-2: w-pair (<13 active)
    const int cog = tid >> 4;     // phase-2: co group of 4
    __syncthreads();

    for (int mi = 0; mi < MT; mi++) {
        const int m = m0 + mi;

        // stage xwin tile (64 x 26 floats, contiguous)
        {
            const float4* src = (const float4*)(g_xwin + ((size_t)(n * LT + m)) * CI * VP);
            float4* dst = (float4*)xw;
            for (int i = tid; i < (CI * VP) / 4; i += 256) dst[i] = src[i];
        }
        __syncthreads();

        // phase 1: y[k, :] = sum_c xw[c,:] * W[c,k]   (packed over v-pairs)
        if (k < KD) {
            unsigned long long acc[13];
            #pragma unroll
            for (int vp = 0; vp < 13; vp++) acc[vp] = 0ull;
            #pragma unroll 4
            for (int c = 0; c < CI; c++) {
                float w = Wsm[c * KD + k];
                unsigned long long w2 = pack2(w, w);
                const unsigned long long* xr = (const unsigned long long*)(xw + c * VP);
                #pragma unroll
                for (int vp = 0; vp < 13; vp++) acc[vp] = ffma2(w2, xr[vp], acc[vp]);
            }
            unsigned long long* yr = (unsigned long long*)(ysm + k * VP);
            #pragma unroll
            for (int vp = 0; vp < 13; vp++) yr[vp] = acc[vp];
        }
        __syncthreads();

        // phase 2 + epilogue: t[co, w-pair] = sum_{p,v} y[co*3+p, v] * A[p,v,w-pair]
        if (wp < 13) {
            unsigned long long tacc[4] = {0ull, 0ull, 0ull, 0ull};
            #pragma unroll
            for (int p = 0; p < 3; p++) {
                #pragma unroll 5
                for (int v = 0; v < V; v++) {
                    unsigned long long a2 = As[(p * V + v) * 13 + wp];
                    #pragma unroll
                    for (int i = 0; i < 4; i++) {
                        int kk = (cog * 4 + i) * 3 + p;
                        float yv = ysm[kk * VP + v];
                        tacc[i] = ffma2(pack2(yv, yv), a2, tacc[i]);
                    }
                }
            }
            const int w0 = 2 * wp;
            #pragma unroll
            for (int i = 0; i < 4; i++) {
                int co = cog * 4 + i;
                float t0, t1;
                unpack2(tacc[i], t0, t1);
                float iv = bnA[co], bb = bnB[co];
                size_t base = ((size_t)((n * CI + co) * LT + m)) * V;
                float r0 = fmaxf(fmaf(t0, iv, bb), 0.f);
                out[base + w0] = fmaxf(r0 + x[base + w0], 0.f);
                if (w0 + 1 < V) {
                    float r1 = fmaxf(fmaf(t1, iv, bb), 0.f);
                    out[base + w0 + 1] = fmaxf(r1 + x[base + w0 + 1], 0.f);
                }
            }
        }
        __syncthreads();
    }
}

extern "C" void kernel_launch(void* const* d_in, const int* in_sizes, int n_in,
                              void* d_out, int out_size) {
    const float* x     = (const float*)d_in[0];
    const float* A     = (const float*)d_in[1];
    const float* W     = (const float*)d_in[2];
    const float* gamma = (const float*)d_in[3];
    const float* beta  = (const float*)d_in[4];
    const float* mean  = (const float*)d_in[5];
    const float* var   = (const float*)d_in[6];
    float* out = (float*)d_out;

    win_kernel<<<NB * CI, 256>>>(x);

    cudaFuncSetAttribute(main_kernel, cudaFuncAttributeMaxDynamicSharedMemorySize, SMEM_BYTES);
    main_kernel<<<NB * (LT / MT), 256, SMEM_BYTES>>>(x, A, W, gamma, beta, mean, var, out);
}